// round 1
// baseline (speedup 1.0000x reference)
#include <cuda_runtime.h>
#include <math.h>

#define B_SZ 32
#define C_SZ 64
#define T_SZ 8192
#define LOGT 13
#define NSPLIT 8
#define TSEG (T_SZ / NSPLIT)   // 1024
#define TC 64

// ---------------- scratch (static device globals; no allocation) ----------------
__device__ float2 g_Z[(size_t)B_SZ * C_SZ * T_SZ];                 // 128 MB phasors
__device__ float  g_Gpart[(size_t)NSPLIT * B_SZ * C_SZ * C_SZ * 2]; // 8 MB partial grams
__device__ float2 g_tw[T_SZ / 2];                                   // twiddles exp(-2pi i k/N)

// ---------------- twiddle init (deterministic, re-run every launch) -------------
__global__ void twiddle_init_kernel() {
    int i = blockIdx.x * blockDim.x + threadIdx.x;
    if (i < T_SZ / 2) {
        double ang = -2.0 * 3.14159265358979323846 * (double)i / (double)T_SZ;
        g_tw[i] = make_float2((float)cos(ang), (float)sin(ang));
    }
}

// ---------------- FFT -> Hilbert filter -> IFFT -> phase normalize --------------
// One block per (b,c) signal. DIF forward produces bit-reversed order; the Hilbert
// multiplier in bit-reversed domain is: p==0 ->1, p==1 ->1 (k=N/2), p even ->2,
// p odd ->0. DIT inverse consumes bit-reversed order and yields natural order.
// The 1/N inverse scale cancels in z/|z| and is skipped.
__global__ __launch_bounds__(512) void fft_hilbert_kernel(const float* __restrict__ x) {
    extern __shared__ float2 s[];   // 8192 * 8B = 64 KB
    const int row = blockIdx.x;
    const float* xr = x + (size_t)row * T_SZ;
    const int tid = threadIdx.x;

    #pragma unroll
    for (int r = 0; r < 16; r++) {
        int t = tid + r * 512;
        s[t] = make_float2(xr[t], 0.f);
    }
    __syncthreads();

    // forward DIF
    #pragma unroll
    for (int st = 0; st < LOGT; st++) {
        const int shift = 12 - st;
        const int half = 1 << shift;
        #pragma unroll
        for (int r = 0; r < 8; r++) {
            int t = tid + r * 512;                 // 0..4095 butterflies
            int blk = t >> shift;
            int j = t & (half - 1);
            int i0 = (blk << (shift + 1)) + j;
            int i1 = i0 + half;
            float2 u = s[i0], v = s[i1];
            float2 w = g_tw[j << st];
            float2 d = make_float2(u.x - v.x, u.y - v.y);
            s[i0] = make_float2(u.x + v.x, u.y + v.y);
            s[i1] = make_float2(d.x * w.x - d.y * w.y, d.x * w.y + d.y * w.x);
        }
        __syncthreads();
    }

    // Hilbert multiplier in bit-reversed domain
    #pragma unroll
    for (int r = 0; r < 16; r++) {
        int p = tid + r * 512;
        if (p >= 2) {
            if (p & 1) s[p] = make_float2(0.f, 0.f);
            else { s[p].x *= 2.f; s[p].y *= 2.f; }
        }
    }
    __syncthreads();

    // inverse DIT (conjugate twiddles, scale skipped)
    #pragma unroll
    for (int st = 0; st < LOGT; st++) {
        const int half = 1 << st;
        #pragma unroll
        for (int r = 0; r < 8; r++) {
            int t = tid + r * 512;
            int blk = t >> st;
            int j = t & (half - 1);
            int i0 = (blk << (st + 1)) + j;
            int i1 = i0 + half;
            float2 w = g_tw[j << (12 - st)];       // use conj(w)
            float2 v = s[i1];
            float2 vw = make_float2(v.x * w.x + v.y * w.y, v.y * w.x - v.x * w.y);
            float2 u = s[i0];
            s[i0] = make_float2(u.x + vw.x, u.y + vw.y);
            s[i1] = make_float2(u.x - vw.x, u.y - vw.y);
        }
        __syncthreads();
    }

    // Z = z / |z|
    float2* Zr = g_Z + (size_t)row * T_SZ;
    #pragma unroll
    for (int r = 0; r < 16; r++) {
        int t = tid + r * 512;
        float2 z = s[t];
        float inv = rsqrtf(z.x * z.x + z.y * z.y);
        Zr[t] = make_float2(z.x * inv, z.y * inv);
    }
}

// ---------------- PLV gram partials: G[b][i][j] = sum_t Z_i conj(Z_j) -----------
// grid (NSPLIT, B). 256 threads, 4x4 register tile per thread, stride-65 smem pad.
__global__ __launch_bounds__(256) void gram_kernel() {
    __shared__ float2 Zs[TC][65];
    const int split = blockIdx.x;
    const int b = blockIdx.y;
    const int tid = threadIdx.x;
    const int tx = tid & 15, ty = tid >> 4;

    float accr[4][4] = {}, acci[4][4] = {};
    const float2* Zb = g_Z + (size_t)b * C_SZ * T_SZ;
    const int tstart = split * TSEG;

    for (int ch = 0; ch < TSEG / TC; ch++) {
        const int tb = tstart + ch * TC;
        #pragma unroll
        for (int l = 0; l < (C_SZ * TC) / 256; l++) {   // 16 iters
            int idx = l * 256 + tid;
            int t = idx & (TC - 1);
            int c = idx >> 6;
            Zs[t][c] = Zb[(size_t)c * T_SZ + tb + t];
        }
        __syncthreads();
        #pragma unroll 4
        for (int t = 0; t < TC; t++) {
            float2 a[4], bb[4];
            #pragma unroll
            for (int r = 0; r < 4; r++) a[r] = Zs[t][ty + 16 * r];
            #pragma unroll
            for (int c = 0; c < 4; c++) bb[c] = Zs[t][tx + 16 * c];
            #pragma unroll
            for (int r = 0; r < 4; r++)
                #pragma unroll
                for (int c = 0; c < 4; c++) {
                    accr[r][c] += a[r].x * bb[c].x + a[r].y * bb[c].y;
                    acci[r][c] += a[r].y * bb[c].x - a[r].x * bb[c].y;
                }
        }
        __syncthreads();
    }

    float* Gp = g_Gpart + ((size_t)(split * B_SZ + b)) * (C_SZ * C_SZ * 2);
    #pragma unroll
    for (int r = 0; r < 4; r++)
        #pragma unroll
        for (int c = 0; c < 4; c++) {
            int R = ty + 16 * r, Cc = tx + 16 * c;
            Gp[(R * 64 + Cc) * 2]     = accr[r][c];
            Gp[(R * 64 + Cc) * 2 + 1] = acci[r][c];
        }
}

// ---------------- tail: connectivity finalize + GCN + MHA, one block per batch --
#define SM_A   4160                  // s_conn: [64][65]
#define SM_B   (SM_A + 8256)         // s_F1:   [64][129]
#define SM_T2  (SM_B + 8256)         // s_h1:   [64][129]
#define SM_H2  (SM_T2 + 4160)        // s_t2:   [64][65]
#define TAIL_FLOATS (SM_H2 + 4160)   // s_h2:   [64][65]  -> 28992 floats = 113.3 KB

__global__ __launch_bounds__(256) void tail_kernel(
    const float* __restrict__ EE,  const float* __restrict__ w1, const float* __restrict__ b1,
    const float* __restrict__ w2,  const float* __restrict__ b2,
    const float* __restrict__ Wip, const float* __restrict__ bip,
    const float* __restrict__ Wop, const float* __restrict__ bop,
    float* __restrict__ out)
{
    extern __shared__ float sm[];
    float* s_conn = sm;
    float* s_F1 = sm + SM_A;
    float* s_h1 = sm + SM_B;
    float* s_t2 = sm + SM_T2;
    float* s_h2 = sm + SM_H2;
    const int b = blockIdx.x;
    const int tid = threadIdx.x;

    // 1. connectivity = |sum splits| / T, zero diagonal; write output #1
    for (int i = tid; i < 4096; i += 256) {
        int r = i >> 6, c = i & 63;
        float re = 0.f, im = 0.f;
        #pragma unroll
        for (int sp = 0; sp < NSPLIT; sp++) {
            const float* Gp = g_Gpart + ((size_t)(sp * B_SZ + b)) * 8192;
            re += Gp[i * 2];
            im += Gp[i * 2 + 1];
        }
        float v = (r == c) ? 0.f : sqrtf(re * re + im * im) * (1.f / (float)T_SZ);
        s_conn[r * 65 + c] = v;
        out[(size_t)b * 4096 + i] = v;
    }
    __syncthreads();

    // 2. F1 = EE @ w1   (64x128)
    for (int i = tid; i < 64 * 128; i += 256) {
        int r = i >> 7, f = i & 127;
        float acc = 0.f;
        for (int e = 0; e < 64; e++) acc += EE[r * 64 + e] * w1[e * 128 + f];
        s_F1[r * 129 + f] = acc;
    }
    __syncthreads();

    // 3. h1 = relu(conn @ F1 + b1)
    for (int i = tid; i < 64 * 128; i += 256) {
        int r = i >> 7, f = i & 127;
        float acc = b1[f];
        for (int j = 0; j < 64; j++) acc += s_conn[r * 65 + j] * s_F1[j * 129 + f];
        s_h1[r * 129 + f] = fmaxf(acc, 0.f);
    }
    __syncthreads();

    // 4a. t2 = h1 @ w2
    for (int i = tid; i < 4096; i += 256) {
        int j = i >> 6, e = i & 63;
        float acc = 0.f;
        for (int f = 0; f < 128; f++) acc += s_h1[j * 129 + f] * w2[f * 64 + e];
        s_t2[j * 65 + e] = acc;
    }
    __syncthreads();

    // 4b. h2 = conn @ t2 + b2; write output #3
    for (int i = tid; i < 4096; i += 256) {
        int r = i >> 6, e = i & 63;
        float acc = b2[e];
        for (int j = 0; j < 64; j++) acc += s_conn[r * 65 + j] * s_t2[j * 65 + e];
        s_h2[r * 65 + e] = acc;
        out[(size_t)(2 * B_SZ * 4096) + (size_t)b * 4096 + i] = acc;
    }
    __syncthreads();

    // 5. qkv = h2 @ Wip^T + bip  (reuse F1/h1 region: q,k,v each [64][65])
    float* s_q = s_F1;
    float* s_k = s_F1 + 4160;
    float* s_v = s_F1 + 8320;
    for (int i = tid; i < 64 * 192; i += 256) {
        int n = i / 192, m = i % 192;
        float acc = bip[m];
        for (int e = 0; e < 64; e++) acc += s_h2[n * 65 + e] * Wip[m * 64 + e];
        float* dst = (m < 64) ? s_q : (m < 128 ? s_k : s_v);
        dst[n * 65 + (m & 63)] = acc;
    }
    __syncthreads();

    // 6. attention: one (head,row) per task; out in s_conn region (conn done)
    float* s_out = s_conn;
    const float inv_sqrt_d = 0.35355339059327373f;  // 1/sqrt(8)
    for (int task = tid; task < 512; task += 256) {
        int h = task >> 6, qi = task & 63;
        float qv[8];
        #pragma unroll
        for (int d = 0; d < 8; d++) qv[d] = s_q[qi * 65 + h * 8 + d];
        float mx = -1e30f;
        for (int k = 0; k < 64; k++) {
            float sc = 0.f;
            #pragma unroll
            for (int d = 0; d < 8; d++) sc += qv[d] * s_k[k * 65 + h * 8 + d];
            mx = fmaxf(mx, sc * inv_sqrt_d);
        }
        float denom = 0.f, acc[8] = {};
        for (int k = 0; k < 64; k++) {
            float sc = 0.f;
            #pragma unroll
            for (int d = 0; d < 8; d++) sc += qv[d] * s_k[k * 65 + h * 8 + d];
            float p = expf(sc * inv_sqrt_d - mx);
            denom += p;
            #pragma unroll
            for (int d = 0; d < 8; d++) acc[d] += p * s_v[k * 65 + h * 8 + d];
        }
        float rinv = 1.f / denom;
        #pragma unroll
        for (int d = 0; d < 8; d++) s_out[qi * 65 + h * 8 + d] = acc[d] * rinv;
    }
    __syncthreads();

    // 7. graph_features = attn_out @ Wop^T + bop; write output #2
    for (int i = tid; i < 4096; i += 256) {
        int n = i >> 6, e = i & 63;
        float acc = bop[e];
        for (int f = 0; f < 64; f++) acc += s_out[n * 65 + f] * Wop[e * 64 + f];
        out[(size_t)(B_SZ * 4096) + (size_t)b * 4096 + i] = acc;
    }
}

// ---------------- launch ----------------
extern "C" void kernel_launch(void* const* d_in, const int* in_sizes, int n_in,
                              void* d_out, int out_size) {
    const float* x   = (const float*)d_in[0];
    const float* EE  = (const float*)d_in[1];
    const float* w1  = (const float*)d_in[2];
    const float* b1  = (const float*)d_in[3];
    const float* w2  = (const float*)d_in[4];
    const float* b2  = (const float*)d_in[5];
    const float* Wip = (const float*)d_in[6];
    const float* bip = (const float*)d_in[7];
    const float* Wop = (const float*)d_in[8];
    const float* bop = (const float*)d_in[9];
    float* out = (float*)d_out;

    cudaFuncSetAttribute(fft_hilbert_kernel,
                         cudaFuncAttributeMaxDynamicSharedMemorySize, 65536);
    cudaFuncSetAttribute(tail_kernel,
                         cudaFuncAttributeMaxDynamicSharedMemorySize, TAIL_FLOATS * 4);

    twiddle_init_kernel<<<16, 256>>>();
    fft_hilbert_kernel<<<B_SZ * C_SZ, 512, 65536>>>(x);
    gram_kernel<<<dim3(NSPLIT, B_SZ), 256>>>();
    tail_kernel<<<B_SZ, 256, TAIL_FLOATS * 4>>>(EE, w1, b1, w2, b2,
                                                Wip, bip, Wop, bop, out);
}

// round 2
// speedup vs baseline: 2.1175x; 2.1175x over previous
#include <cuda_runtime.h>
#include <math.h>

#define B_SZ 32
#define C_SZ 64
#define T_SZ 8192
#define NSPLIT 8
#define TSEG (T_SZ / NSPLIT)   // 1024

// ---------------- scratch (static device globals; no allocation) ----------------
__device__ float2 g_Z[(size_t)B_SZ * C_SZ * T_SZ];                    // 128 MB phasors
__device__ float  g_Gpart[(size_t)NSPLIT * B_SZ * 10 * 256 * 2];      // 5.2 MB tri-tile partials
__device__ float2 g_tw[T_SZ / 2];                                     // exp(-2pi i k/N)

__constant__ int c_TI[10] = {0,0,0,0,1,1,1,2,2,3};
__constant__ int c_TJ[10] = {0,1,2,3,1,2,3,2,3,3};

__device__ __forceinline__ float2 cmul(float2 a, float2 b) {
    return make_float2(a.x * b.x - a.y * b.y, a.x * b.y + a.y * b.x);
}
__device__ __forceinline__ float2 cadd(float2 a, float2 b) { return make_float2(a.x + b.x, a.y + b.y); }
__device__ __forceinline__ float2 csub(float2 a, float2 b) { return make_float2(a.x - b.x, a.y - b.y); }

// ---------------- twiddle init ----------------
__global__ void twiddle_init_kernel() {
    int i = blockIdx.x * blockDim.x + threadIdx.x;
    if (i < T_SZ / 2) {
        double ang = -2.0 * 3.14159265358979323846 * (double)i / (double)T_SZ;
        g_tw[i] = make_float2((float)cos(ang), (float)sin(ang));
    }
}

// ---------------- FFT -> Hilbert -> IFFT -> normalize (2 stages / round trip) ---
// Radix-2 DIF forward (natural -> bit-reversed), Hilbert in bit-reversed domain
// (p==0:1, p==1:1, even:2, odd:0), radix-2 DIT inverse. 1/N scale cancels in z/|z|.
// Consecutive stage pairs fused: one smem round trip per two stages.
__global__ __launch_bounds__(512) void fft_hilbert_kernel(const float* __restrict__ x) {
    extern __shared__ float2 s[];   // 8192 * 8B = 64 KB
    const int row = blockIdx.x;
    const float* xr = x + (size_t)row * T_SZ;
    const int tid = threadIdx.x;

    // ---- fused: load x + forward stage pair (st=0,1). i == g here. ----
    #pragma unroll
    for (int rr = 0; rr < 4; rr++) {
        int g = tid + rr * 512;               // 0..2047
        float u0 = xr[g], u1 = xr[g + 2048], u2 = xr[g + 4096], u3 = xr[g + 6144];
        float2 w1 = g_tw[g];                  // m = j = g
        float2 w2 = g_tw[2 * g];
        float ap = u0 + u2, cd = u0 - u2;
        float bp = u1 + u3, dd = u1 - u3;
        float2 cp = make_float2(cd * w1.x, cd * w1.y);
        float2 dp = make_float2(dd * w1.y, -dd * w1.x);   // dd * (w1 * -i)
        s[g]        = make_float2(ap + bp, 0.f);
        s[g + 2048] = make_float2((ap - bp) * w2.x, (ap - bp) * w2.y);
        s[g + 4096] = cadd(cp, dp);
        s[g + 6144] = cmul(csub(cp, dp), w2);
    }
    __syncthreads();

    // ---- forward stage pairs st = 2,4,6,8,10 ----
    #pragma unroll
    for (int st = 2; st < 12; st += 2) {
        const int shift = 12 - st;
        const int h = 1 << shift, h2 = h >> 1;
        #pragma unroll
        for (int rr = 0; rr < 4; rr++) {
            int g = tid + rr * 512;
            int j = g & (h2 - 1);
            int i = ((g >> (shift - 1)) << (shift + 1)) + j;
            int m = j << st;
            float2 u0 = s[i], u1 = s[i + h2], u2 = s[i + h], u3 = s[i + h + h2];
            float2 w1 = g_tw[m];
            float2 w2 = g_tw[2 * m];
            float2 ap = cadd(u0, u2);
            float2 cp = cmul(csub(u0, u2), w1);
            float2 bp = cadd(u1, u3);
            float2 w1b = make_float2(w1.y, -w1.x);        // w1 * (-i)
            float2 dp = cmul(csub(u1, u3), w1b);
            s[i]          = cadd(ap, bp);
            s[i + h2]     = cmul(csub(ap, bp), w2);
            s[i + h]      = cadd(cp, dp);
            s[i + h + h2] = cmul(csub(cp, dp), w2);
        }
        __syncthreads();
    }

    // ---- fused: final forward stage (st=12, w=1) + Hilbert mask ----
    #pragma unroll
    for (int rr = 0; rr < 8; rr++) {
        int t = tid + rr * 512;               // 0..4095
        float2 u = s[2 * t], v = s[2 * t + 1];
        float2 a = cadd(u, v), d = csub(u, v);
        if (t == 0) { s[0] = a; s[1] = d; }   // k=0 and k=N/2: x1
        else {
            s[2 * t]     = make_float2(2.f * a.x, 2.f * a.y);  // positive freq: x2
            s[2 * t + 1] = make_float2(0.f, 0.f);              // negative freq: x0
        }
    }
    __syncthreads();

    // ---- inverse stage pairs st = 0,2,4,6,8,10 (conjugate twiddles) ----
    #pragma unroll
    for (int st = 0; st < 12; st += 2) {
        const int g1 = 1 << st;
        #pragma unroll
        for (int rr = 0; rr < 4; rr++) {
            int q = tid + rr * 512;
            int j = q & (g1 - 1);
            int i = ((q >> st) << (st + 2)) + j;
            int m = j << (12 - st);
            float2 tm = g_tw[m];
            float2 w  = make_float2(tm.x, -tm.y);          // conj
            float2 t2 = g_tw[m >> 1];
            float2 w2 = make_float2(t2.x, -t2.y);          // conj
            float2 w2b = make_float2(-w2.y, w2.x);         // w2 * i  (= conj(tw*(-i)))
            float2 u0 = s[i], u1 = s[i + g1], u2 = s[i + 2 * g1], u3 = s[i + 3 * g1];
            float2 v1 = cmul(u1, w), v3 = cmul(u3, w);
            float2 p0 = cadd(u0, v1), p1 = csub(u0, v1);
            float2 p2 = cadd(u2, v3), p3 = csub(u2, v3);
            float2 q2 = cmul(p2, w2), q3 = cmul(p3, w2b);
            s[i]           = cadd(p0, q2);
            s[i + 2 * g1]  = csub(p0, q2);
            s[i + g1]      = cadd(p1, q3);
            s[i + 3 * g1]  = csub(p1, q3);
        }
        __syncthreads();
    }

    // ---- fused: final inverse stage (st=12) + normalize + store ----
    float2* Zr = g_Z + (size_t)row * T_SZ;
    #pragma unroll
    for (int rr = 0; rr < 8; rr++) {
        int t = tid + rr * 512;               // 0..4095
        float2 tm = g_tw[t];
        float2 w = make_float2(tm.x, -tm.y);
        float2 u = s[t];
        float2 v = cmul(s[t + 4096], w);
        float2 z0 = cadd(u, v), z1 = csub(u, v);
        float i0 = rsqrtf(z0.x * z0.x + z0.y * z0.y);
        float i1 = rsqrtf(z1.x * z1.x + z1.y * z1.y);
        Zr[t]        = make_float2(z0.x * i0, z0.y * i0);
        Zr[t + 4096] = make_float2(z1.x * i1, z1.y * i1);
    }
}

// ---------------- PLV gram partials, Hermitian: only 10 upper 16x16 tiles -------
// grid (10, NSPLIT, B). 256 threads = 4 t-groups x 64; each 64-group computes the
// 16x16 tile with 2x2 complex register blocks; groups reduced in smem at the end.
__global__ __launch_bounds__(256) void gram_kernel() {
    __shared__ float2 As[16][129];   // stride 129 float2: 2-row step -> distinct banks
    __shared__ float2 Bs[16][129];
    const int z = blockIdx.x, split = blockIdx.y, b = blockIdx.z;
    const int ti = c_TI[z], tj = c_TJ[z];
    const int tid = threadIdx.x;
    const int grp = tid >> 6;        // t-subgroup 0..3
    const int sid = tid & 63;
    const int r2 = sid >> 3, c2 = sid & 7;   // 8x8 thread grid, 2x2 tiles

    float ar00 = 0, ar01 = 0, ar10 = 0, ar11 = 0;
    float ai00 = 0, ai01 = 0, ai10 = 0, ai11 = 0;

    const float2* ZA = g_Z + ((size_t)b * C_SZ + ti * 16) * T_SZ;
    const float2* ZB = g_Z + ((size_t)b * C_SZ + tj * 16) * T_SZ;
    const int tstart = split * TSEG;

    for (int ch = 0; ch < 8; ch++) {
        const int tb = tstart + ch * 128;
        #pragma unroll
        for (int l = tid; l < 2048; l += 256) {
            int rw = l >> 7, t = l & 127;
            As[rw][t] = ZA[(size_t)rw * T_SZ + tb + t];
            Bs[rw][t] = ZB[(size_t)rw * T_SZ + tb + t];
        }
        __syncthreads();
        const int t0 = grp * 32;
        #pragma unroll 8
        for (int t = 0; t < 32; t++) {
            float2 a0 = As[2 * r2][t0 + t],  a1 = As[2 * r2 + 1][t0 + t];
            float2 b0 = Bs[2 * c2][t0 + t],  b1 = Bs[2 * c2 + 1][t0 + t];
            ar00 += a0.x * b0.x + a0.y * b0.y;  ai00 += a0.y * b0.x - a0.x * b0.y;
            ar01 += a0.x * b1.x + a0.y * b1.y;  ai01 += a0.y * b1.x - a0.x * b1.y;
            ar10 += a1.x * b0.x + a1.y * b0.y;  ai10 += a1.y * b0.x - a1.x * b0.y;
            ar11 += a1.x * b1.x + a1.y * b1.y;  ai11 += a1.y * b1.x - a1.x * b1.y;
        }
        __syncthreads();
    }

    // reduce the 4 t-groups via smem (reuse As)
    float* red = (float*)As;   // need 2048 floats; As holds 4128 float2
    float* my = red + (sid * 4 + grp) * 8;
    my[0] = ar00; my[1] = ai00; my[2] = ar01; my[3] = ai01;
    my[4] = ar10; my[5] = ai10; my[6] = ar11; my[7] = ai11;
    __syncthreads();
    if (grp == 0) {
        float v[8];
        #pragma unroll
        for (int k = 0; k < 8; k++)
            v[k] = red[(sid * 4 + 0) * 8 + k] + red[(sid * 4 + 1) * 8 + k]
                 + red[(sid * 4 + 2) * 8 + k] + red[(sid * 4 + 3) * 8 + k];
        float* Gp = g_Gpart + (((size_t)(split * B_SZ + b)) * 10 + z) * 512;
        #pragma unroll
        for (int rr = 0; rr < 2; rr++)
            #pragma unroll
            for (int cc = 0; cc < 2; cc++) {
                int R = 2 * r2 + rr, C = 2 * c2 + cc;
                Gp[(R * 16 + C) * 2]     = v[(rr * 2 + cc) * 2];
                Gp[(R * 16 + C) * 2 + 1] = v[(rr * 2 + cc) * 2 + 1];
            }
    }
}

// ---------------- tail: conn finalize + GCN + MHA. One block/batch, 512 thr -----
#define OFF_EE   4160
#define OFF_F1   8320
#define OFF_H1   16768
#define OFF_T2   25216
#define OFF_H2   29632
#define OFF_Q    34048
#define OFF_K    38464
#define OFF_V    42880
#define TAIL_FLOATS 47296   // 189184 bytes

__global__ __launch_bounds__(512) void tail_kernel(
    const float* __restrict__ EE,  const float* __restrict__ w1, const float* __restrict__ b1,
    const float* __restrict__ w2,  const float* __restrict__ b2,
    const float* __restrict__ Wip, const float* __restrict__ bip,
    const float* __restrict__ Wop, const float* __restrict__ bop,
    float* __restrict__ out)
{
    extern __shared__ float sm[];
    float* s_conn = sm;                 // [64][65]
    float* s_EE  = sm + OFF_EE;         // [64][65]
    float* s_F1  = sm + OFF_F1;         // [64][132]
    float* s_h1  = sm + OFF_H1;         // [64][132]
    float* s_t2  = sm + OFF_T2;         // [64][69]
    float* s_h2  = sm + OFF_H2;         // [64][69]
    float* s_q   = sm + OFF_Q;          // [64][69]
    float* s_k   = sm + OFF_K;
    float* s_v   = sm + OFF_V;
    float* s_ao  = s_conn;              // conn dead after h2
    const int b = blockIdx.x;
    const int tid = threadIdx.x;

    // EE -> smem
    for (int i = tid; i < 4096; i += 512)
        s_EE[(i >> 6) * 65 + (i & 63)] = EE[i];

    // connectivity: reduce 8 split-partials, Hermitian fill, |.|/T, zero diag
    for (int i = tid; i < 4096; i += 512) {
        int r = i >> 6, c = i & 63;
        int bi = r >> 4, bj = c >> 4, rr = r & 15, cc = c & 15;
        int ii = bi, jj = bj, o1 = rr, o2 = cc;
        if (bi > bj) { ii = bj; jj = bi; o1 = cc; o2 = rr; }
        int til = 4 * ii - ((ii * (ii - 1)) >> 1) + (jj - ii);
        int off = (til * 256 + o1 * 16 + o2) * 2;
        float re = 0.f, im = 0.f;
        #pragma unroll
        for (int sp = 0; sp < 8; sp++) {
            const float* Gp = g_Gpart + ((size_t)(sp * B_SZ + b)) * (10 * 512);
            re += Gp[off]; im += Gp[off + 1];
        }
        float v = (r == c) ? 0.f : sqrtf(re * re + im * im) * (1.f / (float)T_SZ);
        s_conn[r * 65 + c] = v;
        out[(size_t)b * 4096 + i] = v;
    }
    __syncthreads();

    // F1 = EE @ w1  (paired rows share weight loads)
    for (int i = tid; i < 4096; i += 512) {
        int f = i & 127, r = i >> 7;
        float a0 = 0.f, a1 = 0.f;
        #pragma unroll 4
        for (int e = 0; e < 64; e++) {
            float w = w1[e * 128 + f];
            a0 += s_EE[r * 65 + e] * w;
            a1 += s_EE[(r + 32) * 65 + e] * w;
        }
        s_F1[r * 132 + f] = a0;
        s_F1[(r + 32) * 132 + f] = a1;
    }
    __syncthreads();

    // h1 = relu(conn @ F1 + b1)
    for (int i = tid; i < 4096; i += 512) {
        int f = i & 127, r = i >> 7;
        float bb = b1[f];
        float a0 = bb, a1 = bb;
        #pragma unroll 4
        for (int j = 0; j < 64; j++) {
            float fv = s_F1[j * 132 + f];
            a0 += s_conn[r * 65 + j] * fv;
            a1 += s_conn[(r + 32) * 65 + j] * fv;
        }
        s_h1[r * 132 + f] = fmaxf(a0, 0.f);
        s_h1[(r + 32) * 132 + f] = fmaxf(a1, 0.f);
    }
    __syncthreads();

    // t2 = h1 @ w2
    for (int i = tid; i < 2048; i += 512) {
        int e = i & 63, r = i >> 6;
        float a0 = 0.f, a1 = 0.f;
        #pragma unroll 4
        for (int f = 0; f < 128; f++) {
            float w = w2[f * 64 + e];
            a0 += s_h1[r * 132 + f] * w;
            a1 += s_h1[(r + 32) * 132 + f] * w;
        }
        s_t2[r * 69 + e] = a0;
        s_t2[(r + 32) * 69 + e] = a1;
    }
    __syncthreads();

    // h2 = conn @ t2 + b2 ; output #3
    for (int i = tid; i < 2048; i += 512) {
        int e = i & 63, r = i >> 6;
        float bb = b2[e];
        float a0 = bb, a1 = bb;
        #pragma unroll 4
        for (int j = 0; j < 64; j++) {
            float t = s_t2[j * 69 + e];
            a0 += s_conn[r * 65 + j] * t;
            a1 += s_conn[(r + 32) * 65 + j] * t;
        }
        s_h2[r * 69 + e] = a0;
        s_h2[(r + 32) * 69 + e] = a1;
        out[(size_t)(2 * B_SZ * 4096) + (size_t)b * 4096 + r * 64 + e] = a0;
        out[(size_t)(2 * B_SZ * 4096) + (size_t)b * 4096 + (r + 32) * 64 + e] = a1;
    }
    __syncthreads();

    // qkv = h2 @ Wip^T + bip
    for (int i = tid; i < 6144; i += 512) {
        int n = i & 63, m = i >> 6;            // m in [0,96)
        float a0 = bip[m], a1 = bip[m + 96];
        #pragma unroll 4
        for (int e = 0; e < 64; e++) {
            float h = s_h2[n * 69 + e];
            a0 += h * Wip[m * 64 + e];
            a1 += h * Wip[(m + 96) * 64 + e];
        }
        if (m < 64) s_q[n * 69 + m] = a0; else s_k[n * 69 + (m - 64)] = a0;
        if (m < 32) s_k[n * 69 + (m + 32)] = a1; else s_v[n * 69 + (m - 32)] = a1;
    }
    __syncthreads();

    // attention: 512 tasks = (head, row), one per thread, two-pass softmax
    {
        int h = tid >> 6, qi = tid & 63;
        const float inv_sqrt_d = 0.35355339059327373f;
        float qv[8];
        #pragma unroll
        for (int d = 0; d < 8; d++) qv[d] = s_q[qi * 69 + h * 8 + d];
        float mx = -1e30f;
        for (int k = 0; k < 64; k++) {
            float sc = 0.f;
            #pragma unroll
            for (int d = 0; d < 8; d++) sc += qv[d] * s_k[k * 69 + h * 8 + d];
            mx = fmaxf(mx, sc * inv_sqrt_d);
        }
        float denom = 0.f, acc[8] = {};
        for (int k = 0; k < 64; k++) {
            float sc = 0.f;
            #pragma unroll
            for (int d = 0; d < 8; d++) sc += qv[d] * s_k[k * 69 + h * 8 + d];
            float p = expf(sc * inv_sqrt_d - mx);
            denom += p;
            #pragma unroll
            for (int d = 0; d < 8; d++) acc[d] += p * s_v[k * 69 + h * 8 + d];
        }
        float rinv = 1.f / denom;
        __syncthreads();                  // conn reads fully done; safe to overwrite
        #pragma unroll
        for (int d = 0; d < 8; d++) s_ao[qi * 65 + h * 8 + d] = acc[d] * rinv;
    }
    __syncthreads();

    // graph_features = ao @ Wop^T + bop ; output #2
    for (int i = tid; i < 2048; i += 512) {
        int n = i & 63, e = i >> 6;           // e in [0,32)
        float a0 = bop[e], a1 = bop[e + 32];
        #pragma unroll 4
        for (int f = 0; f < 64; f++) {
            float av = s_ao[n * 65 + f];
            a0 += av * Wop[e * 64 + f];
            a1 += av * Wop[(e + 32) * 64 + f];
        }
        out[(size_t)(B_SZ * 4096) + (size_t)b * 4096 + n * 64 + e] = a0;
        out[(size_t)(B_SZ * 4096) + (size_t)b * 4096 + n * 64 + e + 32] = a1;
    }
}

// ---------------- launch ----------------
extern "C" void kernel_launch(void* const* d_in, const int* in_sizes, int n_in,
                              void* d_out, int out_size) {
    const float* x   = (const float*)d_in[0];
    const float* EE  = (const float*)d_in[1];
    const float* w1  = (const float*)d_in[2];
    const float* b1  = (const float*)d_in[3];
    const float* w2  = (const float*)d_in[4];
    const float* b2  = (const float*)d_in[5];
    const float* Wip = (const float*)d_in[6];
    const float* bip = (const float*)d_in[7];
    const float* Wop = (const float*)d_in[8];
    const float* bop = (const float*)d_in[9];
    float* out = (float*)d_out;

    cudaFuncSetAttribute(fft_hilbert_kernel,
                         cudaFuncAttributeMaxDynamicSharedMemorySize, 65536);
    cudaFuncSetAttribute(tail_kernel,
                         cudaFuncAttributeMaxDynamicSharedMemorySize, TAIL_FLOATS * 4);

    twiddle_init_kernel<<<16, 256>>>();
    fft_hilbert_kernel<<<B_SZ * C_SZ, 512, 65536>>>(x);
    gram_kernel<<<dim3(10, NSPLIT, B_SZ), 256>>>();
    tail_kernel<<<B_SZ, 512, TAIL_FLOATS * 4>>>(EE, w1, b1, w2, b2,
                                                Wip, bip, Wop, bop, out);
}